// round 6
// baseline (speedup 1.0000x reference)
#include <cuda_runtime.h>
#include <cuda_bf16.h>
#include <stdint.h>

#define NN   2048
#define DD   512
#define CC   128
#define BB   4096
#define TOPK 10
#define NBLK 32                  // 4096 / 128 column blocks
#define CAND_PER_ROW (NBLK * TOPK)   // 320

// ---------------- device scratch ----------------
__device__ __align__(16) __nv_bfloat16 g_hi[(size_t)BB * DD];  // 4 MB
__device__ __align__(16) __nv_bfloat16 g_lo[(size_t)BB * DD];  // 4 MB
__device__ __align__(16) unsigned long long g_cand[(size_t)BB * CAND_PER_ROW]; // 10.5 MB
__device__ __align__(16) float g_probs[(size_t)BB * CC];
__device__ float g_sq[BB];
__device__ float g_partial[BB];

// ---------------- helpers ----------------
__device__ __forceinline__ uint32_t smem_u32(const void* p) {
    uint32_t a;
    asm("{ .reg .u64 t; cvta.to.shared.u64 t, %1; cvt.u32.u64 %0, t; }"
        : "=r"(a) : "l"(p));
    return a;
}
__device__ __forceinline__ void ldsm4(uint32_t& r0, uint32_t& r1, uint32_t& r2,
                                      uint32_t& r3, uint32_t addr) {
    asm volatile("ldmatrix.sync.aligned.m8n8.x4.shared.b16 {%0,%1,%2,%3}, [%4];"
                 : "=r"(r0), "=r"(r1), "=r"(r2), "=r"(r3) : "r"(addr));
}
__device__ __forceinline__ void mma16816(float* c, const uint32_t* a,
                                         uint32_t b0, uint32_t b1) {
    asm volatile(
        "mma.sync.aligned.m16n8k16.row.col.f32.bf16.bf16.f32 "
        "{%0,%1,%2,%3}, {%4,%5,%6,%7}, {%8,%9}, {%0,%1,%2,%3};"
        : "+f"(c[0]), "+f"(c[1]), "+f"(c[2]), "+f"(c[3])
        : "r"(a[0]), "r"(a[1]), "r"(a[2]), "r"(a[3]), "r"(b0), "r"(b1));
}
#define CP_ASYNC16(dst, src) \
    asm volatile("cp.async.cg.shared.global [%0], [%1], 16;" :: "r"(dst), "l"(src))
#define CP_COMMIT()  asm volatile("cp.async.commit_group;" ::: "memory")
#define CP_WAIT0()   asm volatile("cp.async.wait_group 0;" ::: "memory")

// sorted-10 insert, ascending, static indexing only
#define INSERT10(a, key) do {                                           \
    if ((key) < a[9]) {                                                 \
        a[9] = (key);                                                   \
        unsigned long long _t;                                          \
        if (a[9] < a[8]) { _t = a[8]; a[8] = a[9]; a[9] = _t; }         \
        if (a[8] < a[7]) { _t = a[7]; a[7] = a[8]; a[8] = _t; }         \
        if (a[7] < a[6]) { _t = a[6]; a[6] = a[7]; a[7] = _t; }         \
        if (a[6] < a[5]) { _t = a[5]; a[5] = a[6]; a[6] = _t; }         \
        if (a[5] < a[4]) { _t = a[4]; a[4] = a[5]; a[5] = _t; }         \
        if (a[4] < a[3]) { _t = a[3]; a[3] = a[4]; a[4] = _t; }         \
        if (a[3] < a[2]) { _t = a[2]; a[2] = a[3]; a[3] = _t; }         \
        if (a[2] < a[1]) { _t = a[1]; a[1] = a[2]; a[2] = _t; }         \
        if (a[1] < a[0]) { _t = a[0]; a[0] = a[1]; a[1] = _t; }         \
    }                                                                   \
} while (0)

// ---------------- pack: bf16 hi/lo split + probs copy ----------------
__global__ void pack_kernel(const float* __restrict__ zi, const float* __restrict__ zj,
                            const float* __restrict__ pi, const float* __restrict__ pj) {
    const int total_f4 = NN * DD / 4;
    const int total_p4 = NN * CC / 4;
    for (int i4 = blockIdx.x * blockDim.x + threadIdx.x; i4 < total_f4;
         i4 += gridDim.x * blockDim.x) {
        float4 a = ((const float4*)zi)[i4];
        float4 b = ((const float4*)zj)[i4];
        float av[4] = {a.x, a.y, a.z, a.w};
        float bv[4] = {b.x, b.y, b.z, b.w};
        __nv_bfloat16 ah[4], al[4], bh[4], bl[4];
        #pragma unroll
        for (int e = 0; e < 4; e++) {
            ah[e] = __float2bfloat16(av[e]);
            al[e] = __float2bfloat16(av[e] - __bfloat162float(ah[e]));
            bh[e] = __float2bfloat16(bv[e]);
            bl[e] = __float2bfloat16(bv[e] - __bfloat162float(bh[e]));
        }
        __nv_bfloat162* hi2 = (__nv_bfloat162*)g_hi;
        __nv_bfloat162* lo2 = (__nv_bfloat162*)g_lo;
        hi2[2 * i4]     = __nv_bfloat162{ah[0], ah[1]};
        hi2[2 * i4 + 1] = __nv_bfloat162{ah[2], ah[3]};
        lo2[2 * i4]     = __nv_bfloat162{al[0], al[1]};
        lo2[2 * i4 + 1] = __nv_bfloat162{al[2], al[3]};
        const int off = total_f4;
        hi2[2 * (off + i4)]     = __nv_bfloat162{bh[0], bh[1]};
        hi2[2 * (off + i4) + 1] = __nv_bfloat162{bh[2], bh[3]};
        lo2[2 * (off + i4)]     = __nv_bfloat162{bl[0], bl[1]};
        lo2[2 * (off + i4) + 1] = __nv_bfloat162{bl[2], bl[3]};
        if (i4 < total_p4) {
            ((float4*)g_probs)[i4]            = ((const float4*)pi)[i4];
            ((float4*)g_probs)[total_p4 + i4] = ((const float4*)pj)[i4];
        }
    }
}

// ---------------- row squared norms (fp32 originals) ----------------
__global__ void sqnorm_kernel(const float* __restrict__ zi, const float* __restrict__ zj) {
    int warp = (blockIdx.x * blockDim.x + threadIdx.x) >> 5;
    int lane = threadIdx.x & 31;
    if (warp >= BB) return;
    const float* row = (warp < NN) ? (zi + (size_t)warp * DD)
                                   : (zj + (size_t)(warp - NN) * DD);
    float s = 0.f;
    #pragma unroll
    for (int q = 0; q < 4; q++) {
        float4 v = *(const float4*)(row + (q * 32 + lane) * 4);
        s += v.x * v.x + v.y * v.y + v.z * v.z + v.w * v.w;
    }
    #pragma unroll
    for (int off = 16; off > 0; off >>= 1)
        s += __shfl_down_sync(0xffffffffu, s, off);
    if (lane == 0) g_sq[warp] = s;
}

// ---------------- mma.sync distance GEMM + fused per-tile top-10 ----------------
#define BUF_B   10240            // 128 * 80
#define STAGE_B (4 * BUF_B)      // 40960
#define DSMEM_B (2 * STAGE_B)    // 81920 (epilogue reuses 66048 + 1024)

extern __shared__ char dynsm[];

__global__ void __launch_bounds__(256, 1) dist_gemm_mma() {
    int t = blockIdx.x;
    int bi = 0;
    while (t >= 32 - bi) { t -= 32 - bi; bi++; }
    const int bj = bi + t;

    const int tid  = threadIdx.x;
    const int wid  = tid >> 5;
    const int lane = tid & 31;
    const int wm   = (wid >> 2) * 64;
    const int wn   = (wid & 3) * 32;

    const uint32_t sbase = smem_u32(dynsm);

    const __nv_bfloat16* src[8];
    uint32_t dst[8];
    #pragma unroll
    for (int it = 0; it < 8; it++) {
        const int cid = it * 256 + tid;
        const int b   = cid >> 9;
        const int w   = cid & 511;
        const int row = w >> 2;
        const int seg = w & 3;
        const int grow = ((b < 2) ? bi : bj) * 128 + row;
        src[it] = ((b & 1) ? g_lo : g_hi) + (size_t)grow * DD + seg * 8;
        dst[it] = sbase + b * BUF_B + row * 80 + seg * 16;
    }

    float acc[4][4][4];
    #pragma unroll
    for (int fm = 0; fm < 4; fm++)
        #pragma unroll
        for (int fn = 0; fn < 4; fn++)
            #pragma unroll
            for (int e = 0; e < 4; e++) acc[fm][fn][e] = 0.f;

    #pragma unroll
    for (int it = 0; it < 8; it++) CP_ASYNC16(dst[it], src[it]);
    CP_COMMIT();

    for (int ch = 0; ch < 16; ch++) {
        CP_WAIT0();
        __syncthreads();
        if (ch < 15) {
            const uint32_t soff = ((ch + 1) & 1) * STAGE_B;
            #pragma unroll
            for (int it = 0; it < 8; it++)
                CP_ASYNC16(dst[it] + soff, src[it] + (ch + 1) * 32);
            CP_COMMIT();
        }
        const uint32_t stg = sbase + (ch & 1) * STAGE_B;

        #pragma unroll
        for (int kst = 0; kst < 2; kst++) {
            const uint32_t ko = kst * 32 + (lane >> 4) * 16;
            uint32_t ahi[4][4], alo[4][4];
            #pragma unroll
            for (int fm = 0; fm < 4; fm++) {
                const uint32_t ra = (wm + fm * 16 + (lane & 15)) * 80 + ko;
                ldsm4(ahi[fm][0], ahi[fm][1], ahi[fm][2], ahi[fm][3], stg + ra);
                ldsm4(alo[fm][0], alo[fm][1], alo[fm][2], alo[fm][3],
                      stg + BUF_B + ra);
            }
            uint32_t bh[2][4], bl[2][4];
            #pragma unroll
            for (int fp = 0; fp < 2; fp++) {
                const uint32_t rb = (wn + fp * 16 + (lane & 15)) * 80 + ko;
                ldsm4(bh[fp][0], bh[fp][1], bh[fp][2], bh[fp][3],
                      stg + 2 * BUF_B + rb);
                ldsm4(bl[fp][0], bl[fp][1], bl[fp][2], bl[fp][3],
                      stg + 3 * BUF_B + rb);
            }
            #pragma unroll
            for (int fm = 0; fm < 4; fm++)
                #pragma unroll
                for (int fn = 0; fn < 4; fn++) {
                    const int fp = fn >> 1, s = fn & 1;
                    mma16816(acc[fm][fn], ahi[fm], bh[fp][s], bh[fp][s + 2]);
                    mma16816(acc[fm][fn], ahi[fm], bl[fp][s], bl[fp][s + 2]);
                    mma16816(acc[fm][fn], alo[fm], bh[fp][s], bh[fp][s + 2]);
                }
        }
        __syncthreads();
    }

    // ---------------- epilogue: dots -> smem, fused top-10 candidates ----------------
    float* smf = (float*)dynsm;                    // 128 x 129 dots
    float* sqa = (float*)(dynsm + 66048);          // 128 sq_i (block bi)
    float* sqb = (float*)(dynsm + 66048 + 512);    // 128 sq_j (block bj)

    if (tid < 128) {
        sqa[tid] = g_sq[bi * 128 + tid];
        sqb[tid] = g_sq[bj * 128 + tid];
    }
    const int grp = lane >> 2, qc = (lane & 3) * 2;
    #pragma unroll
    for (int fm = 0; fm < 4; fm++) {
        const int m0 = wm + fm * 16 + grp;
        #pragma unroll
        for (int fn = 0; fn < 4; fn++) {
            const int n0 = wn + fn * 8 + qc;
            smf[m0 * 129 + n0]           = acc[fm][fn][0];
            smf[m0 * 129 + n0 + 1]       = acc[fm][fn][1];
            smf[(m0 + 8) * 129 + n0]     = acc[fm][fn][2];
            smf[(m0 + 8) * 129 + n0 + 1] = acc[fm][fn][3];
        }
    }
    __syncthreads();

    // thread-per-row serial scan with sorted-10 insertion (exact u64 keys)
    const int half = tid >> 7;          // 0: direct rows (block bi), 1: mirror rows (block bj)
    const int m    = tid & 127;
    unsigned long long a[10];
    #pragma unroll
    for (int q = 0; q < 10; q++) a[q] = 0xFFFFFFFFFFFFFFFFull;

    if (half == 0) {
        const float si = sqa[m];
        #pragma unroll 4
        for (int n = 0; n < 128; n++) {
            const float d2 = fmaxf(fmaf(-2.f, smf[m * 129 + n], si + sqb[n]), 0.f);
            unsigned long long key =
                ((unsigned long long)__float_as_uint(d2) << 32) |
                (unsigned)(bj * 128 + n);
            if (bi == bj && n == m) key = 0xFFFFFFFFFFFFFFFFull;  // self
            INSERT10(a, key);
        }
        unsigned long long* out =
            g_cand + (size_t)(bi * 128 + m) * CAND_PER_ROW + bj * TOPK;
        #pragma unroll
        for (int q = 0; q < 10; q++) out[q] = a[q];
    } else if (bi != bj) {
        const float sj = sqb[m];
        #pragma unroll 4
        for (int c = 0; c < 128; c++) {
            const float d2 = fmaxf(fmaf(-2.f, smf[c * 129 + m], sqa[c] + sj), 0.f);
            unsigned long long key =
                ((unsigned long long)__float_as_uint(d2) << 32) |
                (unsigned)(bi * 128 + c);
            INSERT10(a, key);
        }
        unsigned long long* out =
            g_cand + (size_t)(bj * 128 + m) * CAND_PER_ROW + bi * TOPK;
        #pragma unroll
        for (int q = 0; q < 10; q++) out[q] = a[q];
    }
}

// ---------------- pass 2: merge 32 sorted slots -> global top-10, loss ----------------
__global__ void __launch_bounds__(256) pass2_kernel(const int* __restrict__ labels) {
    const int wid  = threadIdx.x >> 5;
    const int lane = threadIdx.x & 31;
    const int r    = blockIdx.x * 8 + wid;

    __shared__ unsigned long long s_win[8][TOPK];

    // lane = slot; each slot's 10 candidates are sorted ascending
    const unsigned long long* base =
        g_cand + (size_t)r * CAND_PER_ROW + lane * TOPK;
    unsigned long long v[10];
    #pragma unroll
    for (int q = 0; q < 10; q++) v[q] = base[q];

    #pragma unroll
    for (int sel = 0; sel < TOPK; sel++) {
        unsigned long long h = v[0];
        unsigned long long w = h;
        #pragma unroll
        for (int o = 16; o > 0; o >>= 1)
            w = min(w, __shfl_xor_sync(0xffffffffu, w, o));
        if (lane == 0) s_win[wid][sel] = w;
        if (h == w) {  // unique key: exactly one lane pops
            #pragma unroll
            for (int q = 0; q < 9; q++) v[q] = v[q + 1];
            v[9] = 0xFFFFFFFFFFFFFFFFull;
        }
    }
    __syncwarp();

    const float radius =
        sqrtf(__uint_as_float((unsigned)(s_win[wid][0] >> 32)));
    const int lr = labels[r & (NN - 1)];

    float sum = 0.f;
    #pragma unroll
    for (int t2 = 0; t2 < TOPK; t2++) {
        const unsigned long long win = s_win[wid][t2];
        const int   j  = (int)(win & 0xFFFFFFFFu);
        const float pd = sqrtf(__uint_as_float((unsigned)(win >> 32)));
        const float w  = 1.f - fminf(fmaxf((pd - radius) / radius, 0.f), 1.f);

        const int lj = labels[j & (NN - 1)];
        const bool msk = (lr == lj) && (lr != -1) && (lj != -1) &&
                         ((r & (NN - 1)) != (j & (NN - 1)));

        float4 pa = *(const float4*)(g_probs + (size_t)r * CC + lane * 4);
        float4 pb = *(const float4*)(g_probs + (size_t)j * CC + lane * 4);
        float s = pa.x * pb.x + pa.y * pb.y + pa.z * pb.z + pa.w * pb.w;
        #pragma unroll
        for (int o = 16; o > 0; o >>= 1)
            s += __shfl_down_sync(0xffffffffu, s, o);
        if (lane == 0) sum += msk ? (w * s) : 0.f;   // fixed t2 order
    }
    if (lane == 0) g_partial[r] = sum;
}

// ---------------- deterministic final reduction ----------------
__global__ void __launch_bounds__(1024) finalize_kernel(float* __restrict__ out) {
    __shared__ float sm[1024];
    const int tid = threadIdx.x;
    float s = g_partial[tid] + g_partial[tid + 1024] +
              g_partial[tid + 2048] + g_partial[tid + 3072];
    sm[tid] = s;
    __syncthreads();
    for (int sfx = 512; sfx > 0; sfx >>= 1) {
        if (tid < sfx) sm[tid] += sm[tid + sfx];
        __syncthreads();
    }
    if (tid == 0) out[0] = sm[0] / (float)((size_t)BB * BB);
}

// ---------------- launch ----------------
extern "C" void kernel_launch(void* const* d_in, const int* in_sizes, int n_in,
                              void* d_out, int out_size) {
    const float* zi = (const float*)d_in[0];
    const float* zj = (const float*)d_in[1];
    const float* pi = (const float*)d_in[2];
    const float* pj = (const float*)d_in[3];
    const int*   pl = (const int*)d_in[4];
    float* out = (float*)d_out;

    static int cfg = 0;
    if (!cfg) {
        cudaFuncSetAttribute(dist_gemm_mma,
                             cudaFuncAttributeMaxDynamicSharedMemorySize, DSMEM_B);
        cfg = 1;
    }

    pack_kernel<<<1024, 256>>>(zi, zj, pi, pj);
    sqnorm_kernel<<<(BB * 32 + 127) / 128, 128>>>(zi, zj);
    dist_gemm_mma<<<528, 256, DSMEM_B>>>();
    pass2_kernel<<<512, 256>>>(pl);
    finalize_kernel<<<1, 1024>>>(out);
}

// round 7
// speedup vs baseline: 2.0771x; 2.0771x over previous
#include <cuda_runtime.h>
#include <cuda_bf16.h>
#include <stdint.h>

#define NN   2048
#define DD   512
#define CC   128
#define BB   4096
#define TOPK 10
#define KSEL 12

// ---------------- device scratch ----------------
__device__ __align__(16) __nv_bfloat16 g_hi[(size_t)BB * DD];   // 4 MB
__device__ __align__(16) unsigned short g_pdq[(size_t)BB * BB]; // 32 MB quantized d2
__device__ __align__(16) float g_probs[(size_t)BB * CC];
__device__ __align__(16) int   g_cand[(size_t)BB * KSEL];
__device__ float g_sq[BB];
__device__ float g_partial[BB];

// ---------------- helpers ----------------
__device__ __forceinline__ uint32_t smem_u32(const void* p) {
    uint32_t a;
    asm("{ .reg .u64 t; cvta.to.shared.u64 t, %1; cvt.u32.u64 %0, t; }"
        : "=r"(a) : "l"(p));
    return a;
}
__device__ __forceinline__ void ldsm4(uint32_t& r0, uint32_t& r1, uint32_t& r2,
                                      uint32_t& r3, uint32_t addr) {
    asm volatile("ldmatrix.sync.aligned.m8n8.x4.shared.b16 {%0,%1,%2,%3}, [%4];"
                 : "=r"(r0), "=r"(r1), "=r"(r2), "=r"(r3) : "r"(addr));
}
__device__ __forceinline__ void mma16816(float* c, const uint32_t* a,
                                         uint32_t b0, uint32_t b1) {
    asm volatile(
        "mma.sync.aligned.m16n8k16.row.col.f32.bf16.bf16.f32 "
        "{%0,%1,%2,%3}, {%4,%5,%6,%7}, {%8,%9}, {%0,%1,%2,%3};"
        : "+f"(c[0]), "+f"(c[1]), "+f"(c[2]), "+f"(c[3])
        : "r"(a[0]), "r"(a[1]), "r"(a[2]), "r"(a[3]), "r"(b0), "r"(b1));
}
#define CP_ASYNC16(dst, src) \
    asm volatile("cp.async.cg.shared.global [%0], [%1], 16;" :: "r"(dst), "l"(src))
#define CP_COMMIT()  asm volatile("cp.async.commit_group;" ::: "memory")
#define CP_WAIT0()   asm volatile("cp.async.wait_group 0;" ::: "memory")

__device__ __forceinline__ unsigned short quant16(float d2) {
    int q = (int)(d2 * 16.f);
    q = max(0, min(q, 65534));
    return (unsigned short)q;
}

// ---------------- pack: bf16 hi + probs copy ----------------
__global__ void pack_kernel(const float* __restrict__ zi, const float* __restrict__ zj,
                            const float* __restrict__ pi, const float* __restrict__ pj) {
    const int total_f4 = NN * DD / 4;
    const int total_p4 = NN * CC / 4;
    for (int i4 = blockIdx.x * blockDim.x + threadIdx.x; i4 < total_f4;
         i4 += gridDim.x * blockDim.x) {
        float4 a = ((const float4*)zi)[i4];
        float4 b = ((const float4*)zj)[i4];
        __nv_bfloat162* hi2 = (__nv_bfloat162*)g_hi;
        hi2[2 * i4]     = __nv_bfloat162{__float2bfloat16(a.x), __float2bfloat16(a.y)};
        hi2[2 * i4 + 1] = __nv_bfloat162{__float2bfloat16(a.z), __float2bfloat16(a.w)};
        const int off = total_f4;
        hi2[2 * (off + i4)]     = __nv_bfloat162{__float2bfloat16(b.x), __float2bfloat16(b.y)};
        hi2[2 * (off + i4) + 1] = __nv_bfloat162{__float2bfloat16(b.z), __float2bfloat16(b.w)};
        if (i4 < total_p4) {
            ((float4*)g_probs)[i4]            = ((const float4*)pi)[i4];
            ((float4*)g_probs)[total_p4 + i4] = ((const float4*)pj)[i4];
        }
    }
}

// ---------------- row squared norms (fp32 originals) ----------------
__global__ void sqnorm_kernel(const float* __restrict__ zi, const float* __restrict__ zj) {
    int warp = (blockIdx.x * blockDim.x + threadIdx.x) >> 5;
    int lane = threadIdx.x & 31;
    if (warp >= BB) return;
    const float* row = (warp < NN) ? (zi + (size_t)warp * DD)
                                   : (zj + (size_t)(warp - NN) * DD);
    float s = 0.f;
    #pragma unroll
    for (int q = 0; q < 4; q++) {
        float4 v = *(const float4*)(row + (q * 32 + lane) * 4);
        s += v.x * v.x + v.y * v.y + v.z * v.z + v.w * v.w;
    }
    #pragma unroll
    for (int off = 16; off > 0; off >>= 1)
        s += __shfl_down_sync(0xffffffffu, s, off);
    if (lane == 0) g_sq[warp] = s;
}

// ---------------- 1-product bf16 GEMM -> quantized d2 ----------------
#define BUF_B   10240            // 128 rows * 80 B
#define STAGE_B (2 * BUF_B)      // A, B buffers
#define DSMEM_B 67072            // max(mainloop 40960, epilogue 66048+1024)

extern __shared__ char dynsm[];

__global__ void __launch_bounds__(256, 1) dist_gemm_mma() {
    int t = blockIdx.x;
    int bi = 0;
    while (t >= 32 - bi) { t -= 32 - bi; bi++; }
    const int bj = bi + t;

    const int tid  = threadIdx.x;
    const int wid  = tid >> 5;
    const int lane = tid & 31;
    const int wm   = (wid >> 2) * 64;
    const int wn   = (wid & 3) * 32;

    const uint32_t sbase = smem_u32(dynsm);

    const __nv_bfloat16* src[4];
    uint32_t dst[4];
    #pragma unroll
    for (int it = 0; it < 4; it++) {
        const int cid = it * 256 + tid;        // 0..1023
        const int b   = cid >> 9;              // 0: A rows, 1: B rows
        const int w   = cid & 511;
        const int row = w >> 2;
        const int seg = w & 3;
        const int grow = ((b == 0) ? bi : bj) * 128 + row;
        src[it] = g_hi + (size_t)grow * DD + seg * 8;
        dst[it] = sbase + b * BUF_B + row * 80 + seg * 16;
    }

    float acc[4][4][4];
    #pragma unroll
    for (int fm = 0; fm < 4; fm++)
        #pragma unroll
        for (int fn = 0; fn < 4; fn++)
            #pragma unroll
            for (int e = 0; e < 4; e++) acc[fm][fn][e] = 0.f;

    #pragma unroll
    for (int it = 0; it < 4; it++) CP_ASYNC16(dst[it], src[it]);
    CP_COMMIT();

    for (int ch = 0; ch < 16; ch++) {
        CP_WAIT0();
        __syncthreads();
        if (ch < 15) {
            const uint32_t soff = ((ch + 1) & 1) * STAGE_B;
            #pragma unroll
            for (int it = 0; it < 4; it++)
                CP_ASYNC16(dst[it] + soff, src[it] + (ch + 1) * 32);
            CP_COMMIT();
        }
        const uint32_t stg = sbase + (ch & 1) * STAGE_B;

        #pragma unroll
        for (int kst = 0; kst < 2; kst++) {
            const uint32_t ko = kst * 32 + (lane >> 4) * 16;
            uint32_t ahi[4][4];
            #pragma unroll
            for (int fm = 0; fm < 4; fm++) {
                const uint32_t ra = (wm + fm * 16 + (lane & 15)) * 80 + ko;
                ldsm4(ahi[fm][0], ahi[fm][1], ahi[fm][2], ahi[fm][3], stg + ra);
            }
            uint32_t bh[2][4];
            #pragma unroll
            for (int fp = 0; fp < 2; fp++) {
                const uint32_t rb = (wn + fp * 16 + (lane & 15)) * 80 + ko;
                ldsm4(bh[fp][0], bh[fp][1], bh[fp][2], bh[fp][3],
                      stg + BUF_B + rb);
            }
            #pragma unroll
            for (int fm = 0; fm < 4; fm++)
                #pragma unroll
                for (int fn = 0; fn < 4; fn++) {
                    const int fp = fn >> 1, s = fn & 1;
                    mma16816(acc[fm][fn], ahi[fm], bh[fp][s], bh[fp][s + 2]);
                }
        }
        __syncthreads();
    }

    // ---------------- epilogue: dots -> smem -> quantized d2 stores ----------------
    float* smf = (float*)dynsm;                    // 128 x 129 dots
    float* sqa = (float*)(dynsm + 66048);
    float* sqb = (float*)(dynsm + 66048 + 512);

    if (tid < 128) {
        sqa[tid] = g_sq[bi * 128 + tid];
        sqb[tid] = g_sq[bj * 128 + tid];
    }
    const int grp = lane >> 2, qc = (lane & 3) * 2;
    #pragma unroll
    for (int fm = 0; fm < 4; fm++) {
        const int m0 = wm + fm * 16 + grp;
        #pragma unroll
        for (int fn = 0; fn < 4; fn++) {
            const int n0 = wn + fn * 8 + qc;
            smf[m0 * 129 + n0]           = acc[fm][fn][0];
            smf[m0 * 129 + n0 + 1]       = acc[fm][fn][1];
            smf[(m0 + 8) * 129 + n0]     = acc[fm][fn][2];
            smf[(m0 + 8) * 129 + n0 + 1] = acc[fm][fn][3];
        }
    }
    __syncthreads();

    // direct rows (coalesced ushort4)
    #pragma unroll
    for (int it = 0; it < 16; it++) {
        const int mr = it * 8 + wid;
        const float si = sqa[mr];
        ushort4 v;
        v.x = quant16(fmaf(-2.f, smf[mr * 129 + lane * 4 + 0], si + sqb[lane * 4 + 0]));
        v.y = quant16(fmaf(-2.f, smf[mr * 129 + lane * 4 + 1], si + sqb[lane * 4 + 1]));
        v.z = quant16(fmaf(-2.f, smf[mr * 129 + lane * 4 + 2], si + sqb[lane * 4 + 2]));
        v.w = quant16(fmaf(-2.f, smf[mr * 129 + lane * 4 + 3], si + sqb[lane * 4 + 3]));
        if (bi == bj) {   // self -> max sentinel
            if (mr == lane * 4 + 0) v.x = 65535;
            if (mr == lane * 4 + 1) v.y = 65535;
            if (mr == lane * 4 + 2) v.z = 65535;
            if (mr == lane * 4 + 3) v.w = 65535;
        }
        *(ushort4*)(g_pdq + (size_t)(bi * 128 + mr) * BB + bj * 128 + lane * 4) = v;
    }
    // mirror rows
    if (bi != bj) {
        #pragma unroll
        for (int it = 0; it < 16; it++) {
            const int nr = it * 8 + wid;
            const float sj = sqb[nr];
            ushort4 v;
            v.x = quant16(fmaf(-2.f, smf[(lane * 4 + 0) * 129 + nr], sqa[lane * 4 + 0] + sj));
            v.y = quant16(fmaf(-2.f, smf[(lane * 4 + 1) * 129 + nr], sqa[lane * 4 + 1] + sj));
            v.z = quant16(fmaf(-2.f, smf[(lane * 4 + 2) * 129 + nr], sqa[lane * 4 + 2] + sj));
            v.w = quant16(fmaf(-2.f, smf[(lane * 4 + 3) * 129 + nr], sqa[lane * 4 + 3] + sj));
            *(ushort4*)(g_pdq + (size_t)(bj * 128 + nr) * BB + bi * 128 + lane * 4) = v;
        }
    }
}

// ---------------- approx top-12 per row (u32 keys: q<<12 | j) ----------------
__global__ void __launch_bounds__(256) topk12_kernel() {
    const int r    = blockIdx.x;
    const int tid  = threadIdx.x;
    const int lane = tid & 31;
    const int wid  = tid >> 5;
    const unsigned INFK = 0xFFFFFFFFu;

    __shared__ unsigned swm[2][8];
    __shared__ unsigned s_win[KSEL];

    const uint4* rowq = (const uint4*)(g_pdq + (size_t)r * BB);

    unsigned v[16];
    #pragma unroll
    for (int h = 0; h < 2; h++) {
        uint4 p = rowq[tid * 2 + h];
        const unsigned w0 = p.x, w1 = p.y, w2 = p.z, w3 = p.w;
        const int jb = tid * 16 + h * 8;
        v[h * 8 + 0] = ((w0 & 0xFFFFu) << 12) | (jb + 0);
        v[h * 8 + 1] = ((w0 >> 16) << 12)     | (jb + 1);
        v[h * 8 + 2] = ((w1 & 0xFFFFu) << 12) | (jb + 2);
        v[h * 8 + 3] = ((w1 >> 16) << 12)     | (jb + 3);
        v[h * 8 + 4] = ((w2 & 0xFFFFu) << 12) | (jb + 4);
        v[h * 8 + 5] = ((w2 >> 16) << 12)     | (jb + 5);
        v[h * 8 + 6] = ((w3 & 0xFFFFu) << 12) | (jb + 6);
        v[h * 8 + 7] = ((w3 >> 16) << 12)     | (jb + 7);
    }

    unsigned loc = v[0];
    #pragma unroll
    for (int k = 1; k < 16; k++) loc = min(loc, v[k]);

    #pragma unroll
    for (int sel = 0; sel < KSEL; sel++) {
        const int p = sel & 1;
        unsigned wmn = loc;
        #pragma unroll
        for (int o = 16; o > 0; o >>= 1)
            wmn = min(wmn, __shfl_xor_sync(0xffffffffu, wmn, o));
        if (lane == 0) swm[p][wid] = wmn;
        __syncthreads();
        unsigned win = swm[p][0];
        #pragma unroll
        for (int i = 1; i < 8; i++) win = min(win, swm[p][i]);
        if (tid == 0) s_win[sel] = win;
        if (loc == win) {   // unique key: exactly one owner pops
            loc = INFK;
            #pragma unroll
            for (int k = 0; k < 16; k++) {
                if (v[k] == win) v[k] = INFK;
                loc = min(loc, v[k]);
            }
        }
        __syncthreads();
    }

    if (tid < KSEL) g_cand[(size_t)r * KSEL + tid] = (int)(s_win[tid] & 0xFFFu);
}

// ---------------- exact refine of 12 candidates + masked loss ----------------
__global__ void __launch_bounds__(128) refine_loss_kernel(
    const float* __restrict__ zi, const float* __restrict__ zj,
    const int* __restrict__ labels) {
    const int r    = blockIdx.x;
    const int tid  = threadIdx.x;
    const int lane = tid & 31;
    const int wid  = tid >> 5;

    __shared__ int s_j[KSEL];
    __shared__ unsigned long long s_key[KSEL];
    __shared__ float s_con[TOPK];
    __shared__ float s_rad;

    if (tid < KSEL) s_j[tid] = g_cand[(size_t)r * KSEL + tid];
    if (tid < TOPK) s_con[tid] = 0.f;
    __syncthreads();

    const float* rowr = (r < NN) ? (zi + (size_t)r * DD) : (zj + (size_t)(r - NN) * DD);
    const float sqr = g_sq[r];

    // exact fp32 d2 for the 12 candidates (3 per warp)
    for (int t = wid; t < KSEL; t += 4) {
        const int j = s_j[t];
        const float* rowc = (j < NN) ? (zi + (size_t)j * DD)
                                     : (zj + (size_t)(j - NN) * DD);
        float s = 0.f;
        #pragma unroll
        for (int q = 0; q < 4; q++) {
            float4 a = *(const float4*)(rowr + (q * 32 + lane) * 4);
            float4 b = *(const float4*)(rowc + (q * 32 + lane) * 4);
            s += a.x * b.x + a.y * b.y + a.z * b.z + a.w * b.w;
        }
        #pragma unroll
        for (int o = 16; o > 0; o >>= 1)
            s += __shfl_down_sync(0xffffffffu, s, o);
        if (lane == 0) {
            const float d2 = fmaxf(fmaf(-2.f, s, sqr + g_sq[j]), 0.f);
            s_key[t] = ((unsigned long long)__float_as_uint(d2) << 32) | (unsigned)j;
        }
    }
    __syncthreads();

    // exact sort of 12 keys (lexicographic (d2, j)) by one thread
    if (tid == 0) {
        #pragma unroll
        for (int a2 = 1; a2 < KSEL; a2++) {
            unsigned long long key = s_key[a2];
            int b2 = a2 - 1;
            while (b2 >= 0 && s_key[b2] > key) { s_key[b2 + 1] = s_key[b2]; b2--; }
            s_key[b2 + 1] = key;
        }
        s_rad = sqrtf(__uint_as_float((unsigned)(s_key[0] >> 32)));
    }
    __syncthreads();

    const float radius = s_rad;
    const int lr = labels[r & (NN - 1)];

    for (int t = wid; t < TOPK; t += 4) {
        const unsigned long long key = s_key[t];
        const int   j  = (int)(key & 0xFFFFFFFFu);
        const float pd = sqrtf(__uint_as_float((unsigned)(key >> 32)));
        const float w  = 1.f - fminf(fmaxf((pd - radius) / radius, 0.f), 1.f);

        const int lj = labels[j & (NN - 1)];
        const bool msk = (lr == lj) && (lr != -1) && (lj != -1) &&
                         ((r & (NN - 1)) != (j & (NN - 1)));

        float4 pa = *(const float4*)(g_probs + (size_t)r * CC + lane * 4);
        float4 pb = *(const float4*)(g_probs + (size_t)j * CC + lane * 4);
        float s = pa.x * pb.x + pa.y * pb.y + pa.z * pb.z + pa.w * pb.w;
        #pragma unroll
        for (int o = 16; o > 0; o >>= 1)
            s += __shfl_down_sync(0xffffffffu, s, o);
        if (lane == 0) s_con[t] = msk ? (w * s) : 0.f;
    }
    __syncthreads();

    if (tid == 0) {
        float sum = 0.f;
        #pragma unroll
        for (int t = 0; t < TOPK; t++) sum += s_con[t];
        g_partial[r] = sum;
    }
}

// ---------------- deterministic final reduction ----------------
__global__ void __launch_bounds__(1024) finalize_kernel(float* __restrict__ out) {
    __shared__ float sm[1024];
    const int tid = threadIdx.x;
    float s = g_partial[tid] + g_partial[tid + 1024] +
              g_partial[tid + 2048] + g_partial[tid + 3072];
    sm[tid] = s;
    __syncthreads();
    for (int sfx = 512; sfx > 0; sfx >>= 1) {
        if (tid < sfx) sm[tid] += sm[tid + sfx];
        __syncthreads();
    }
    if (tid == 0) out[0] = sm[0] / (float)((size_t)BB * BB);
}

// ---------------- launch ----------------
extern "C" void kernel_launch(void* const* d_in, const int* in_sizes, int n_in,
                              void* d_out, int out_size) {
    const float* zi = (const float*)d_in[0];
    const float* zj = (const float*)d_in[1];
    const float* pi = (const float*)d_in[2];
    const float* pj = (const float*)d_in[3];
    const int*   pl = (const int*)d_in[4];
    float* out = (float*)d_out;

    static int cfg = 0;
    if (!cfg) {
        cudaFuncSetAttribute(dist_gemm_mma,
                             cudaFuncAttributeMaxDynamicSharedMemorySize, DSMEM_B);
        cfg = 1;
    }

    pack_kernel<<<1024, 256>>>(zi, zj, pi, pj);
    sqnorm_kernel<<<1024, 128>>>(zi, zj);
    dist_gemm_mma<<<528, 256, DSMEM_B>>>();
    topk12_kernel<<<BB, 256>>>();
    refine_loss_kernel<<<BB, 128>>>(zi, zj, pl);
    finalize_kernel<<<1, 1024>>>(out);
}